// round 5
// baseline (speedup 1.0000x reference)
#include <cuda_runtime.h>
#include <mma.h>
#include <math.h>

using namespace nvcuda;

#define TT 256      // timesteps
#define BB 256      // batch
#define DD 1024     // hidden dim
#define WS 2048     // W row stride (W is (D, 2D) row-major)

// ===========================================================================
// Kernel 1: preactivations, tf32 wmma, 128x128 tile, double-buffered.
//   out[(b*TT + t)*DD + d] = bias[d] + sum_k x[(t*BB+b)*DD + k] * W[d*WS + k]
// ===========================================================================
#define X_BM 128
#define X_BN 128
#define X_BK 32
#define X_LD 40                       // padded smem ldm
#define X_TILE (X_BM * X_LD)          // 5120 floats
#define X_SMEM_FLOATS (4 * X_TILE)    // A0,B0,A1,B1 = 20480 floats (80 KB)

__global__ void __launch_bounds__(256)
gemm_x_tf32(const float* __restrict__ x, const float* __restrict__ W,
            const float* __restrict__ bias, float* __restrict__ out)
{
    extern __shared__ float sm[];
    float* sA[2] = { sm,              sm + 2 * X_TILE };
    float* sB[2] = { sm + X_TILE,     sm + 3 * X_TILE };

    const int r0  = blockIdx.y * X_BM;   // row tile in (t*BB + b) space
    const int d0  = blockIdx.x * X_BN;
    const int tid = threadIdx.x;
    const int wid = tid >> 5;
    const int warpM = wid & 3;           // 4 x 32 rows
    const int warpN = wid >> 2;          // 2 x 64 cols

    wmma::fragment<wmma::accumulator, 16, 16, 8, float> acc[2][4];
    #pragma unroll
    for (int mi = 0; mi < 2; ++mi)
        #pragma unroll
        for (int ni = 0; ni < 4; ++ni)
            wmma::fill_fragment(acc[mi][ni], 0.0f);

    auto load_chunk = [&](int k0, float* dA, float* dB) {
        #pragma unroll
        for (int j = 0; j < 4; ++j) {
            int f   = tid + j * 256;     // 1024 float4
            int row = f >> 3;            // 8 float4 per row (32 floats)
            int c4  = f & 7;
            float4 va = *reinterpret_cast<const float4*>(
                &x[(size_t)(r0 + row) * DD + k0 + c4 * 4]);
            float* pa = &dA[row * X_LD + c4 * 4];
            pa[0] = wmma::__float_to_tf32(va.x);
            pa[1] = wmma::__float_to_tf32(va.y);
            pa[2] = wmma::__float_to_tf32(va.z);
            pa[3] = wmma::__float_to_tf32(va.w);
            float4 vb = *reinterpret_cast<const float4*>(
                &W[(size_t)(d0 + row) * WS + k0 + c4 * 4]);
            float* pb = &dB[row * X_LD + c4 * 4];
            pb[0] = wmma::__float_to_tf32(vb.x);
            pb[1] = wmma::__float_to_tf32(vb.y);
            pb[2] = wmma::__float_to_tf32(vb.z);
            pb[3] = wmma::__float_to_tf32(vb.w);
        }
    };

    load_chunk(0, sA[0], sB[0]);
    __syncthreads();

    const int NCH = DD / X_BK;           // 32 chunks
    for (int c = 0; c < NCH; ++c) {
        int cur = c & 1;
        if (c + 1 < NCH) load_chunk((c + 1) * X_BK, sA[cur ^ 1], sB[cur ^ 1]);

        #pragma unroll
        for (int kk = 0; kk < X_BK; kk += 8) {
            wmma::fragment<wmma::matrix_a, 16, 16, 8, wmma::precision::tf32, wmma::row_major> a[2];
            #pragma unroll
            for (int mi = 0; mi < 2; ++mi)
                wmma::load_matrix_sync(a[mi], &sA[cur][(warpM * 32 + mi * 16) * X_LD + kk], X_LD);
            #pragma unroll
            for (int ni = 0; ni < 4; ++ni) {
                wmma::fragment<wmma::matrix_b, 16, 16, 8, wmma::precision::tf32, wmma::col_major> b;
                wmma::load_matrix_sync(b, &sB[cur][(warpN * 64 + ni * 16) * X_LD + kk], X_LD);
                #pragma unroll
                for (int mi = 0; mi < 2; ++mi)
                    wmma::mma_sync(acc[mi][ni], a[mi], b, acc[mi][ni]);
            }
        }
        __syncthreads();
    }

    // Stage C in smem (alias buffers: 16384 <= 20480 floats)
    float* sC = sm;
    #pragma unroll
    for (int mi = 0; mi < 2; ++mi)
        #pragma unroll
        for (int ni = 0; ni < 4; ++ni)
            wmma::store_matrix_sync(&sC[(warpM * 32 + mi * 16) * X_BN + warpN * 64 + ni * 16],
                                    acc[mi][ni], X_BN, wmma::mem_row_major);
    __syncthreads();

    // Epilogue: +bias, scatter. Block spans 128 rows => t constant.
    const int t = r0 >> 8;
    const int bbase = r0 & 255;
    #pragma unroll
    for (int j = 0; j < 16; ++j) {
        int f   = tid + j * 256;         // 4096 float4
        int row = f >> 5;                // 32 float4 per row
        int c4  = f & 31;
        float4 bv = *reinterpret_cast<const float4*>(&bias[d0 + c4 * 4]);
        const float* cp = &sC[row * X_BN + c4 * 4];
        float4 o;
        o.x = cp[0] + bv.x; o.y = cp[1] + bv.y; o.z = cp[2] + bv.z; o.w = cp[3] + bv.w;
        *reinterpret_cast<float4*>(
            &out[((size_t)((bbase + row) * TT + t)) * DD + d0 + c4 * 4]) = o;
    }
}

// ===========================================================================
// Kernel 2: persistent recurrence.
// 128 blocks x 512 threads; block tile = 32 batch x 64 d.
// 8 INDEPENDENT batch groups of 16 blocks; group-scoped acq/rel barrier
// with nanosleep backoff. Count and phase words live on separate 256B lines.
// ===========================================================================
#define R_BM 32
#define R_BN 64
#define R_BK 64
#define R_ALD 72
#define R_BLD 72
#define R_ATILE (R_BM * R_ALD)          // 2304
#define R_BTILE (R_BN * R_BLD)          // 4608
#define R_GRPBLK 16                     // blocks per barrier group
// smem: A0 | B0 | A1 | B1 | C(32x64)
#define R_OFF_C (2 * (R_ATILE + R_BTILE))
#define R_SMEM_FLOATS (R_OFF_C + R_BM * R_BN)   // 15872 floats = 63.5 KB

// 8 groups; each group's words at [g*64] -> 256B apart; cnt/phase in
// different arrays (different lines).
__device__ __align__(256) unsigned g_cnt[8 * 64];
__device__ __align__(256) unsigned g_phase[8 * 64];   // monotonic across replays

__device__ __forceinline__ unsigned bar_arrive_acqrel(unsigned* p) {
    unsigned old;
    asm volatile("atom.acq_rel.gpu.add.u32 %0,[%1],1;"
                 : "=r"(old) : "l"(p) : "memory");
    return old;
}
__device__ __forceinline__ void bar_reset_relaxed(unsigned* p) {
    asm volatile("st.relaxed.gpu.u32 [%0],0;" :: "l"(p) : "memory");
}
__device__ __forceinline__ void bar_release(unsigned* p) {
    asm volatile("red.release.gpu.add.u32 [%0],1;" :: "l"(p) : "memory");
}
__device__ __forceinline__ unsigned bar_poll_acquire(const unsigned* p) {
    unsigned v;
    asm volatile("ld.acquire.gpu.u32 %0,[%1];" : "=r"(v) : "l"(p) : "memory");
    return v;
}

__global__ void __launch_bounds__(512)
rnn_persistent(const float* __restrict__ W, float* __restrict__ out)
{
    extern __shared__ float sm[];
    float* sA[2] = { sm,                    sm + R_ATILE + R_BTILE };
    float* sB[2] = { sm + R_ATILE,          sm + 2 * R_ATILE + R_BTILE };
    float* sC    = sm + R_OFF_C;
    __shared__ unsigned s_base;

    const int tid = threadIdx.x;
    const int wid = tid >> 5;        // 16 warps = 2(M) x 4(N) x 2(K-half)
    const int kHalf = wid >> 3;
    const int w8    = wid & 7;
    const int wM    = w8 & 1;
    const int wN    = w8 >> 1;

    const int nT = blockIdx.x & 15;  // 16 d-stripes
    const int mT = blockIdx.x >> 4;  // 8 batch groups (barrier scope!)
    const int d0 = nT * R_BN;
    const int b0 = mT * R_BM;

    unsigned* cntp   = &g_cnt[mT * 64];
    unsigned* phasep = &g_phase[mT * 64];

    const float* Wh = W + DD;

    if (tid == 0) s_base = bar_poll_acquire(phasep);
    __syncthreads();
    const unsigned base = s_base;

    // loaders: A tile 32x64 = 512 float4 (1/thread); B tile 64x64 = 1024 float4
    auto load_h = [&](int tprev, int k0, float* dst) {
        int row = tid >> 4;              // 16 float4 per row
        int c4  = tid & 15;
        float4 v = __ldcg(reinterpret_cast<const float4*>(
            &out[((size_t)((b0 + row) * TT + tprev)) * DD + k0 + c4 * 4]));
        float* p = &dst[row * R_ALD + c4 * 4];
        p[0] = wmma::__float_to_tf32(v.x);
        p[1] = wmma::__float_to_tf32(v.y);
        p[2] = wmma::__float_to_tf32(v.z);
        p[3] = wmma::__float_to_tf32(v.w);
    };
    auto load_w = [&](int k0, float* dst) {
        #pragma unroll
        for (int j = 0; j < 2; ++j) {
            int f   = tid + j * 512;
            int row = f >> 4;
            int c4  = f & 15;
            float4 v = *reinterpret_cast<const float4*>(
                &Wh[(size_t)(d0 + row) * WS + k0 + c4 * 4]);
            float* p = &dst[row * R_BLD + c4 * 4];
            p[0] = wmma::__float_to_tf32(v.x);
            p[1] = wmma::__float_to_tf32(v.y);
            p[2] = wmma::__float_to_tf32(v.z);
            p[3] = wmma::__float_to_tf32(v.w);
        }
    };

    for (int t = 0; t < TT; ++t) {
        if (t == 0) {
            // h0 = 0: out tile = tanh(preact). 512 float4, 1/thread.
            int row = tid >> 4;
            int c4  = tid & 15;
            float* p = &out[((size_t)((b0 + row) * TT + 0)) * DD + d0 + c4 * 4];
            float4 v = __ldcg(reinterpret_cast<const float4*>(p));
            v.x = tanhf(v.x); v.y = tanhf(v.y); v.z = tanhf(v.z); v.w = tanhf(v.w);
            *reinterpret_cast<float4*>(p) = v;
        } else {
            // Prefetch this thread's preactivation early (independent of h)
            const int erow = tid >> 4;
            const int ec4  = tid & 15;
            float* eptr = &out[((size_t)((b0 + erow) * TT + t)) * DD + d0 + ec4 * 4];
            float4 pre = __ldcg(reinterpret_cast<const float4*>(eptr));

            wmma::fragment<wmma::accumulator, 16, 16, 8, float> acc[4];
            #pragma unroll
            for (int i = 0; i < 4; ++i) wmma::fill_fragment(acc[i], 0.0f);

            load_h(t - 1, 0, sA[0]);
            load_w(0, sB[0]);
            __syncthreads();

            const int NCH = DD / R_BK;               // 16 chunks
            for (int c = 0; c < NCH; ++c) {
                int cur = c & 1;
                if (c + 1 < NCH) {
                    load_h(t - 1, (c + 1) * R_BK, sA[cur ^ 1]);
                    load_w((c + 1) * R_BK, sB[cur ^ 1]);
                }
                const float* ap = &sA[cur][wM * 16 * R_ALD + kHalf * 32];
                const float* bp = &sB[cur][wN * 16 * R_BLD + kHalf * 32];
                #pragma unroll
                for (int kk = 0; kk < 32; kk += 8) {
                    wmma::fragment<wmma::matrix_a, 16, 16, 8, wmma::precision::tf32, wmma::row_major> a;
                    wmma::fragment<wmma::matrix_b, 16, 16, 8, wmma::precision::tf32, wmma::col_major> b;
                    wmma::load_matrix_sync(a, ap + kk, R_ALD);
                    wmma::load_matrix_sync(b, bp + kk, R_BLD);
                    wmma::mma_sync(acc[kk >> 3], a, b, acc[kk >> 3]);
                }
                __syncthreads();
            }

            // Reduce 4 K-split accs within warp
            #pragma unroll
            for (int i = 1; i < 4; ++i)
                #pragma unroll
                for (int e = 0; e < acc[0].num_elements; ++e)
                    acc[0].x[e] += acc[i].x[e];

            // Combine K-half warps: kHalf 0 -> sC, kHalf 1 -> scratch (sA[0])
            if (kHalf == 0)
                wmma::store_matrix_sync(&sC[(wM * 16) * R_BN + wN * 16], acc[0],
                                        R_BN, wmma::mem_row_major);
            else
                wmma::store_matrix_sync(&sA[0][(wM * 16) * R_BN + wN * 16], acc[0],
                                        R_BN, wmma::mem_row_major);
            __syncthreads();

            // Epilogue: sC + scratch + preact -> tanh -> store in place
            {
                const float* scratch = sA[0];
                const float* c0 = &sC[erow * R_BN + ec4 * 4];
                const float* c1 = &scratch[erow * R_BN + ec4 * 4];
                float4 o;
                o.x = tanhf(pre.x + c0[0] + c1[0]);
                o.y = tanhf(pre.y + c0[1] + c1[1]);
                o.z = tanhf(pre.z + c0[2] + c1[2]);
                o.w = tanhf(pre.w + c0[3] + c1[3]);
                *reinterpret_cast<float4*>(eptr) = o;
            }
        }

        // Group barrier (16 blocks sharing this batch group), skip after last step
        if (t != TT - 1) {
            __syncthreads();
            if (tid == 0) {
                unsigned old = bar_arrive_acqrel(cntp);
                if (old == R_GRPBLK - 1) {
                    bar_reset_relaxed(cntp);     // ordered before release below
                    bar_release(phasep);
                } else {
                    const unsigned target = base + (unsigned)(t + 1);
                    unsigned ns = 64;
                    while ((int)(bar_poll_acquire(phasep) - target) < 0) {
                        __nanosleep(ns);
                        if (ns < 2048) ns <<= 1;
                    }
                }
            }
            __syncthreads();
        }
    }
}

// ===========================================================================
// Launch
// ===========================================================================
extern "C" void kernel_launch(void* const* d_in, const int* in_sizes, int n_in,
                              void* d_out, int out_size)
{
    const float* x    = (const float*)d_in[0];
    const float* W    = (const float*)d_in[1];
    const float* bias = (const float*)d_in[2];
    float* out = (float*)d_out;

    cudaFuncSetAttribute(gemm_x_tf32, cudaFuncAttributeMaxDynamicSharedMemorySize,
                         X_SMEM_FLOATS * sizeof(float));
    cudaFuncSetAttribute(rnn_persistent, cudaFuncAttributeMaxDynamicSharedMemorySize,
                         R_SMEM_FLOATS * sizeof(float));

    dim3 g1(DD / X_BN, (TT * BB) / X_BM);   // (8, 512)
    gemm_x_tf32<<<g1, 256, X_SMEM_FLOATS * sizeof(float)>>>(x, W, bias, out);

    rnn_persistent<<<128, 512, R_SMEM_FLOATS * sizeof(float)>>>(W, out);
}

// round 6
// speedup vs baseline: 1.3250x; 1.3250x over previous
#include <cuda_runtime.h>
#include <mma.h>
#include <math.h>
#include <stdint.h>

using namespace nvcuda;

#define TT 256      // timesteps
#define BB 256      // batch
#define DD 1024     // hidden dim
#define WS 2048     // W row stride (W is (D, 2D) row-major)

// ===========================================================================
// Kernel 1: preactivations, tf32 wmma, 128x128 tile, double-buffered.
//   out[(b*TT + t)*DD + d] = bias[d] + sum_k x[(t*BB+b)*DD + k] * W[d*WS + k]
// ===========================================================================
#define X_BM 128
#define X_BN 128
#define X_BK 32
#define X_LD 40                       // padded smem ldm
#define X_TILE (X_BM * X_LD)          // 5120 floats
#define X_SMEM_FLOATS (4 * X_TILE)    // A0,B0,A1,B1 = 20480 floats (80 KB)

__global__ void __launch_bounds__(256)
gemm_x_tf32(const float* __restrict__ x, const float* __restrict__ W,
            const float* __restrict__ bias, float* __restrict__ out)
{
    extern __shared__ float sm[];
    float* sA[2] = { sm,              sm + 2 * X_TILE };
    float* sB[2] = { sm + X_TILE,     sm + 3 * X_TILE };

    const int r0  = blockIdx.y * X_BM;   // row tile in (t*BB + b) space
    const int d0  = blockIdx.x * X_BN;
    const int tid = threadIdx.x;
    const int wid = tid >> 5;
    const int warpM = wid & 3;           // 4 x 32 rows
    const int warpN = wid >> 2;          // 2 x 64 cols

    wmma::fragment<wmma::accumulator, 16, 16, 8, float> acc[2][4];
    #pragma unroll
    for (int mi = 0; mi < 2; ++mi)
        #pragma unroll
        for (int ni = 0; ni < 4; ++ni)
            wmma::fill_fragment(acc[mi][ni], 0.0f);

    auto load_chunk = [&](int k0, float* dA, float* dB) {
        #pragma unroll
        for (int j = 0; j < 4; ++j) {
            int f   = tid + j * 256;     // 1024 float4
            int row = f >> 3;            // 8 float4 per row (32 floats)
            int c4  = f & 7;
            float4 va = *reinterpret_cast<const float4*>(
                &x[(size_t)(r0 + row) * DD + k0 + c4 * 4]);
            float* pa = &dA[row * X_LD + c4 * 4];
            pa[0] = wmma::__float_to_tf32(va.x);
            pa[1] = wmma::__float_to_tf32(va.y);
            pa[2] = wmma::__float_to_tf32(va.z);
            pa[3] = wmma::__float_to_tf32(va.w);
            float4 vb = *reinterpret_cast<const float4*>(
                &W[(size_t)(d0 + row) * WS + k0 + c4 * 4]);
            float* pb = &dB[row * X_LD + c4 * 4];
            pb[0] = wmma::__float_to_tf32(vb.x);
            pb[1] = wmma::__float_to_tf32(vb.y);
            pb[2] = wmma::__float_to_tf32(vb.z);
            pb[3] = wmma::__float_to_tf32(vb.w);
        }
    };

    load_chunk(0, sA[0], sB[0]);
    __syncthreads();

    const int NCH = DD / X_BK;           // 32 chunks
    for (int c = 0; c < NCH; ++c) {
        int cur = c & 1;
        if (c + 1 < NCH) load_chunk((c + 1) * X_BK, sA[cur ^ 1], sB[cur ^ 1]);

        #pragma unroll
        for (int kk = 0; kk < X_BK; kk += 8) {
            wmma::fragment<wmma::matrix_a, 16, 16, 8, wmma::precision::tf32, wmma::row_major> a[2];
            #pragma unroll
            for (int mi = 0; mi < 2; ++mi)
                wmma::load_matrix_sync(a[mi], &sA[cur][(warpM * 32 + mi * 16) * X_LD + kk], X_LD);
            #pragma unroll
            for (int ni = 0; ni < 4; ++ni) {
                wmma::fragment<wmma::matrix_b, 16, 16, 8, wmma::precision::tf32, wmma::col_major> b;
                wmma::load_matrix_sync(b, &sB[cur][(warpN * 64 + ni * 16) * X_LD + kk], X_LD);
                #pragma unroll
                for (int mi = 0; mi < 2; ++mi)
                    wmma::mma_sync(acc[mi][ni], a[mi], b, acc[mi][ni]);
            }
        }
        __syncthreads();
    }

    // Stage C in smem (alias buffers: 16384 <= 20480 floats)
    float* sC = sm;
    #pragma unroll
    for (int mi = 0; mi < 2; ++mi)
        #pragma unroll
        for (int ni = 0; ni < 4; ++ni)
            wmma::store_matrix_sync(&sC[(warpM * 32 + mi * 16) * X_BN + warpN * 64 + ni * 16],
                                    acc[mi][ni], X_BN, wmma::mem_row_major);
    __syncthreads();

    // Epilogue: +bias, scatter. Block spans 128 rows => t constant.
    const int t = r0 >> 8;
    const int bbase = r0 & 255;
    #pragma unroll
    for (int j = 0; j < 16; ++j) {
        int f   = tid + j * 256;         // 4096 float4
        int row = f >> 5;                // 32 float4 per row
        int c4  = f & 31;
        float4 bv = *reinterpret_cast<const float4*>(&bias[d0 + c4 * 4]);
        const float* cp = &sC[row * X_BN + c4 * 4];
        float4 o;
        o.x = cp[0] + bv.x; o.y = cp[1] + bv.y; o.z = cp[2] + bv.z; o.w = cp[3] + bv.w;
        *reinterpret_cast<float4*>(
            &out[((size_t)((bbase + row) * TT + t)) * DD + d0 + c4 * 4]) = o;
    }
}

// ===========================================================================
// Kernel 2: persistent recurrence.
//   - 128 blocks x 512 threads; block tile = 64 batch x 32 d.
//   - Wh stripe (32 x 1024 fp32, RN-rounded to tf32) resident in smem for
//     all 256 steps: per-step global traffic is h only.
//   - h streamed via cp.async (no register dependency -> front latency paid
//     once, then L2-bandwidth streaming), 2-deep ring of 64x128 chunks.
//   - 16 warps = 4(M) x 2(N) x 2(K-split).
//   - 4 independent batch groups of 32 blocks; acq/rel barrier, tight spin.
// ===========================================================================
#define RH_WLD 1032                     // Wh smem ldm (1024 + 8)
#define RH_ALD 132                      // h  smem ldm (128 + 4)
#define RH_BM 64
#define RH_BN 32
#define RH_BK 128
#define RH_NCH (DD / RH_BK)             // 8 chunks
#define RH_GRPBLK 32                    // blocks per barrier group

#define RH_OFF_WH 0
#define RH_OFF_A0 (RH_BN * RH_WLD)                    // 33024
#define RH_OFF_A1 (RH_OFF_A0 + RH_BM * RH_ALD)       // 41472
#define RH_OFF_C0 (RH_OFF_A1 + RH_BM * RH_ALD)       // 49920
#define RH_OFF_C1 (RH_OFF_C0 + RH_BM * RH_BN)        // 51968
#define RH_SMEM_FLOATS (RH_OFF_C1 + RH_BM * RH_BN)   // 54016 floats = 211 KB

__device__ __align__(256) unsigned g_cnt[4 * 64];
__device__ __align__(256) unsigned g_phase[4 * 64];   // monotonic across replays

__device__ __forceinline__ unsigned bar_arrive_acqrel(unsigned* p) {
    unsigned old;
    asm volatile("atom.acq_rel.gpu.add.u32 %0,[%1],1;"
                 : "=r"(old) : "l"(p) : "memory");
    return old;
}
__device__ __forceinline__ void bar_reset_relaxed(unsigned* p) {
    asm volatile("st.relaxed.gpu.u32 [%0],0;" :: "l"(p) : "memory");
}
__device__ __forceinline__ void bar_release(unsigned* p) {
    asm volatile("red.release.gpu.add.u32 [%0],1;" :: "l"(p) : "memory");
}
__device__ __forceinline__ unsigned bar_poll_acquire(const unsigned* p) {
    unsigned v;
    asm volatile("ld.acquire.gpu.u32 %0,[%1];" : "=r"(v) : "l"(p) : "memory");
    return v;
}
__device__ __forceinline__ void cp16(uint32_t saddr, const void* gptr) {
    asm volatile("cp.async.cg.shared.global [%0], [%1], 16;"
                 :: "r"(saddr), "l"(gptr));
}

__global__ void __launch_bounds__(512)
rnn_persistent(const float* __restrict__ W, float* __restrict__ out)
{
    extern __shared__ float sm[];
    float* sWh  = sm + RH_OFF_WH;
    float* sA[2] = { sm + RH_OFF_A0, sm + RH_OFF_A1 };
    float* sC[2] = { sm + RH_OFF_C0, sm + RH_OFF_C1 };
    __shared__ unsigned s_base;

    const int tid = threadIdx.x;
    const int wid = tid >> 5;          // 16 warps
    const int wM    = wid & 3;         // 4 x 16 rows = 64
    const int wN    = (wid >> 2) & 1;  // 2 x 16 cols = 32
    const int kHalf = wid >> 3;        // 2-way K split within each 128 chunk

    const int nT = blockIdx.x & 31;    // 32 d-stripes
    const int mT = blockIdx.x >> 5;    // 4 batch groups (barrier scope)
    const int d0 = nT * RH_BN;
    const int b0 = mT * RH_BM;

    unsigned* cntp   = &g_cnt[mT * 64];
    unsigned* phasep = &g_phase[mT * 64];

    const uint32_t sA_u32[2] = {
        (uint32_t)__cvta_generic_to_shared(sA[0]),
        (uint32_t)__cvta_generic_to_shared(sA[1])
    };

    // --- Load Wh stripe once (RN-rounded to tf32): sWh[d][k], d=0..31 ---
    {
        const float* Wh = W + DD;
        #pragma unroll
        for (int j = 0; j < 16; ++j) {
            int f   = tid + j * 512;       // 8192 float4
            int row = f >> 8;              // 256 float4 per row
            int c4  = f & 255;
            float4 v = *reinterpret_cast<const float4*>(
                &Wh[(size_t)(d0 + row) * WS + c4 * 4]);
            float* p = &sWh[row * RH_WLD + c4 * 4];
            p[0] = wmma::__float_to_tf32(v.x);
            p[1] = wmma::__float_to_tf32(v.y);
            p[2] = wmma::__float_to_tf32(v.z);
            p[3] = wmma::__float_to_tf32(v.w);
        }
    }

    if (tid == 0) s_base = bar_poll_acquire(phasep);
    __syncthreads();
    const unsigned base = s_base;

    // issue one 64x128 h chunk via cp.async: 2048 float4, 4 per thread
    auto issue_chunk = [&](int tprev, int c, int buf) {
        #pragma unroll
        for (int j = 0; j < 4; ++j) {
            int f   = tid + j * 512;
            int row = f >> 5;              // 32 float4 per row
            int c4  = f & 31;
            const void* g = &out[((size_t)((b0 + row) * TT + tprev)) * DD
                                 + c * RH_BK + c4 * 4];
            uint32_t s = sA_u32[buf] + (uint32_t)(row * RH_ALD + c4 * 4) * 4u;
            cp16(s, g);
        }
        asm volatile("cp.async.commit_group;");
    };

    // epilogue thread map: 64x32 = 512 float4, 1 per thread
    const int erow = tid >> 3;             // 8 float4 per row
    const int ec4  = tid & 7;

    for (int t = 0; t < TT; ++t) {
        if (t == 0) {
            float* p = &out[((size_t)((b0 + erow) * TT + 0)) * DD + d0 + ec4 * 4];
            float4 v = *reinterpret_cast<const float4*>(p);
            v.x = tanhf(v.x); v.y = tanhf(v.y); v.z = tanhf(v.z); v.w = tanhf(v.w);
            *reinterpret_cast<float4*>(p) = v;
        } else {
            // prefetch this thread's preactivation (independent of h)
            float* eptr = &out[((size_t)((b0 + erow) * TT + t)) * DD + d0 + ec4 * 4];
            float4 pre = __ldcg(reinterpret_cast<const float4*>(eptr));

            wmma::fragment<wmma::accumulator, 16, 16, 8, float> acc[2];
            wmma::fill_fragment(acc[0], 0.0f);
            wmma::fill_fragment(acc[1], 0.0f);

            issue_chunk(t - 1, 0, 0);
            issue_chunk(t - 1, 1, 1);

            for (int c = 0; c < RH_NCH; ++c) {       // 8 chunks
                if (c == RH_NCH - 1) asm volatile("cp.async.wait_group 0;");
                else                 asm volatile("cp.async.wait_group 1;");
                __syncthreads();

                const float* ap = &sA[c & 1][wM * 16 * RH_ALD + kHalf * 64];
                const float* bp = &sWh[(wN * 16) * RH_WLD + c * RH_BK + kHalf * 64];
                #pragma unroll
                for (int kk = 0; kk < 64; kk += 8) {
                    wmma::fragment<wmma::matrix_a, 16, 16, 8, wmma::precision::tf32, wmma::row_major> a;
                    wmma::fragment<wmma::matrix_b, 16, 16, 8, wmma::precision::tf32, wmma::col_major> b;
                    wmma::load_matrix_sync(a, ap + kk, RH_ALD);
                    wmma::load_matrix_sync(b, bp + kk, RH_WLD);
                    wmma::mma_sync(acc[(kk >> 3) & 1], a, b, acc[(kk >> 3) & 1]);
                }
                __syncthreads();                     // before re-filling this buf
                if (c + 2 < RH_NCH) issue_chunk(t - 1, c + 2, c & 1);
            }

            // reduce K-split accs within warp, combine the 2 kHalf warps via smem
            #pragma unroll
            for (int e = 0; e < acc[0].num_elements; ++e)
                acc[0].x[e] += acc[1].x[e];
            wmma::store_matrix_sync(&sC[kHalf][(wM * 16) * RH_BN + wN * 16],
                                    acc[0], RH_BN, wmma::mem_row_major);
            __syncthreads();

            // epilogue: sC0 + sC1 + preact -> tanh -> store in place
            {
                const float* c0 = &sC[0][erow * RH_BN + ec4 * 4];
                const float* c1 = &sC[1][erow * RH_BN + ec4 * 4];
                float4 o;
                o.x = tanhf(pre.x + c0[0] + c1[0]);
                o.y = tanhf(pre.y + c0[1] + c1[1]);
                o.z = tanhf(pre.z + c0[2] + c1[2]);
                o.w = tanhf(pre.w + c0[3] + c1[3]);
                *reinterpret_cast<float4*>(eptr) = o;
            }
        }

        // group barrier (32 blocks sharing this batch group), skip after last
        if (t != TT - 1) {
            __syncthreads();
            if (tid == 0) {
                unsigned old = bar_arrive_acqrel(cntp);
                if (old == RH_GRPBLK - 1) {
                    bar_reset_relaxed(cntp);
                    bar_release(phasep);
                } else {
                    const unsigned target = base + (unsigned)(t + 1);
                    while ((int)(bar_poll_acquire(phasep) - target) < 0) { }
                }
            }
            __syncthreads();
        }
    }
}

// ===========================================================================
// Launch
// ===========================================================================
extern "C" void kernel_launch(void* const* d_in, const int* in_sizes, int n_in,
                              void* d_out, int out_size)
{
    const float* x    = (const float*)d_in[0];
    const float* W    = (const float*)d_in[1];
    const float* bias = (const float*)d_in[2];
    float* out = (float*)d_out;

    cudaFuncSetAttribute(gemm_x_tf32, cudaFuncAttributeMaxDynamicSharedMemorySize,
                         X_SMEM_FLOATS * sizeof(float));
    cudaFuncSetAttribute(rnn_persistent, cudaFuncAttributeMaxDynamicSharedMemorySize,
                         RH_SMEM_FLOATS * sizeof(float));

    dim3 g1(DD / X_BN, (TT * BB) / X_BM);   // (8, 512)
    gemm_x_tf32<<<g1, 256, X_SMEM_FLOATS * sizeof(float)>>>(x, W, bias, out);

    rnn_persistent<<<128, 512, RH_SMEM_FLOATS * sizeof(float)>>>(W, out);
}